// round 5
// baseline (speedup 1.0000x reference)
#include <cuda_runtime.h>
#include <cstdint>

// Causal SDPA, B=4 H=16 S=2048 D=64, fp32 I/O.
// FA2-style flash attention on mma.sync.m16n8k8 tf32 (base sm_100 target — no tcgen05).
// 8 warps x 16 q-rows, BK=64 kv tiles, Q fragments register-resident,
// K/V/P pre-rounded to tf32 in smem, online softmax in registers.

#define BQ 128
#define BK 64
#define DH 64
#define NT 256
#define LD 68            // smem row stride in floats (272 B): conflict-free frag loads
#define SCALE 0.125f
#define NEG_BIG (-1.0e30f)

static constexpr int S_LEN = 2048;
static constexpr int SK_OFF = 0;              // K tile  [64][LD]
static constexpr int SV_OFF = BK * LD;        // V tile  [64][LD]
static constexpr int SP_OFF = 2 * BK * LD;    // P tile / Q staging [128][LD]
static constexpr int SMEM_BYTES = (2 * BK * LD + BQ * LD) * 4;  // 69632 B

__device__ __forceinline__ float tf32r(float x) {
    uint32_t y;
    asm("cvt.rna.tf32.f32 %0, %1;" : "=r"(y) : "f"(x));
    return __uint_as_float(y);
}

__device__ __forceinline__ void mma8(float c[4], const uint32_t a[4],
                                     uint32_t b0, uint32_t b1) {
    asm volatile(
        "mma.sync.aligned.m16n8k8.row.col.f32.tf32.tf32.f32 "
        "{%0,%1,%2,%3}, {%4,%5,%6,%7}, {%8,%9}, {%0,%1,%2,%3};"
        : "+f"(c[0]), "+f"(c[1]), "+f"(c[2]), "+f"(c[3])
        : "r"(a[0]), "r"(a[1]), "r"(a[2]), "r"(a[3]), "r"(b0), "r"(b1));
}

__device__ __forceinline__ float qmax(float v) {
    v = fmaxf(v, __shfl_xor_sync(0xffffffffu, v, 1));
    v = fmaxf(v, __shfl_xor_sync(0xffffffffu, v, 2));
    return v;
}
__device__ __forceinline__ float qsum(float v) {
    v += __shfl_xor_sync(0xffffffffu, v, 1);
    v += __shfl_xor_sync(0xffffffffu, v, 2);
    return v;
}

__global__ __launch_bounds__(NT, 2)
void fa_mma_kernel(const float* __restrict__ Q,
                   const float* __restrict__ K,
                   const float* __restrict__ V,
                   float* __restrict__ O) {
    extern __shared__ float sm[];
    float* sK = sm + SK_OFF;
    float* sV = sm + SV_OFF;
    float* sP = sm + SP_OFF;
    const uint32_t* uK = (const uint32_t*)sK;
    const uint32_t* uV = (const uint32_t*)sV;
    const uint32_t* uP = (const uint32_t*)sP;

    const int tid  = threadIdx.x;
    const int warp = tid >> 5;
    const int lane = tid & 31;
    const int g    = lane >> 2;   // group id (row within 8)
    const int tq   = lane & 3;    // thread-in-group (col quad)

    const int r0 = warp * 16 + g;     // local q row (a0/a2, c0/c1)
    const int r1 = r0 + 8;            // local q row (a1/a3, c2/c3)

    const int bh = blockIdx.y;
    const int qt = (int)(gridDim.x - 1) - (int)blockIdx.x;  // heavy tiles first
    const int q0 = qt * BQ;

    const float* Qg = Q + ((size_t)bh * S_LEN + q0) * DH;
    const float* Kg = K + (size_t)bh * S_LEN * DH;
    const float* Vg = V + (size_t)bh * S_LEN * DH;
    float*       Og = O + ((size_t)bh * S_LEN + q0) * DH;

    // ---- stage Q (scaled + tf32-rounded) into sP, then lift fragments to regs ----
    for (int i = tid; i < BQ * (DH / 4); i += NT) {
        int row = i >> 4;
        int c4  = (i & 15) << 2;
        float4 v = *(const float4*)(Qg + (size_t)row * DH + c4);
        v.x = tf32r(v.x * SCALE); v.y = tf32r(v.y * SCALE);
        v.z = tf32r(v.z * SCALE); v.w = tf32r(v.w * SCALE);
        *(float4*)&sP[row * LD + c4] = v;
    }
    __syncthreads();

    uint32_t qf[8][4];
    #pragma unroll
    for (int kb = 0; kb < 8; kb++) {
        qf[kb][0] = uP[r0 * LD + kb * 8 + tq];
        qf[kb][1] = uP[r1 * LD + kb * 8 + tq];
        qf[kb][2] = uP[r0 * LD + kb * 8 + tq + 4];
        qf[kb][3] = uP[r1 * LD + kb * 8 + tq + 4];
    }

    float oacc[8][4];
    #pragma unroll
    for (int nb = 0; nb < 8; nb++)
        #pragma unroll
        for (int j = 0; j < 4; j++) oacc[nb][j] = 0.f;
    float m0 = NEG_BIG, m1 = NEG_BIG, l0 = 0.f, l1 = 0.f;

    const int ntiles = 2 * qt + 2;   // kv tiles needed for causal coverage
    for (int kt = 0; kt < ntiles; kt++) {
        const int kv0 = kt * BK;

        __syncthreads();  // previous iteration's readers done with sK/sV

        // ---- stage K,V tiles (tf32-rounded) ----
        for (int i = tid; i < BK * (DH / 4); i += NT) {
            int row = i >> 4;
            int c4  = (i & 15) << 2;
            float4 kv = *(const float4*)(Kg + (size_t)(kv0 + row) * DH + c4);
            kv.x = tf32r(kv.x); kv.y = tf32r(kv.y);
            kv.z = tf32r(kv.z); kv.w = tf32r(kv.w);
            *(float4*)&sK[row * LD + c4] = kv;
            float4 vv = *(const float4*)(Vg + (size_t)(kv0 + row) * DH + c4);
            vv.x = tf32r(vv.x); vv.y = tf32r(vv.y);
            vv.z = tf32r(vv.z); vv.w = tf32r(vv.w);
            *(float4*)&sV[row * LD + c4] = vv;
        }
        __syncthreads();

        // ---- S = Q K^T : per-warp 16 x 64, 64 mmas ----
        float sacc[8][4];
        #pragma unroll
        for (int nb = 0; nb < 8; nb++)
            #pragma unroll
            for (int j = 0; j < 4; j++) sacc[nb][j] = 0.f;

        #pragma unroll
        for (int kb = 0; kb < 8; kb++) {
            #pragma unroll
            for (int nb = 0; nb < 8; nb++) {
                uint32_t b0 = uK[(nb * 8 + g) * LD + kb * 8 + tq];
                uint32_t b1 = uK[(nb * 8 + g) * LD + kb * 8 + tq + 4];
                mma8(sacc[nb], qf[kb], b0, b1);
            }
        }

        // ---- causal mask (only last two kv tiles intersect the diagonal) ----
        if (kt >= ntiles - 2) {
            const int qr0 = q0 + r0;
            const int qr1 = q0 + r1;
            #pragma unroll
            for (int nb = 0; nb < 8; nb++) {
                int c = kv0 + nb * 8 + 2 * tq;
                if (c     > qr0) sacc[nb][0] = NEG_BIG;
                if (c + 1 > qr0) sacc[nb][1] = NEG_BIG;
                if (c     > qr1) sacc[nb][2] = NEG_BIG;
                if (c + 1 > qr1) sacc[nb][3] = NEG_BIG;
            }
        }

        // ---- online softmax ----
        float tm0 = NEG_BIG, tm1 = NEG_BIG;
        #pragma unroll
        for (int nb = 0; nb < 8; nb++) {
            tm0 = fmaxf(tm0, fmaxf(sacc[nb][0], sacc[nb][1]));
            tm1 = fmaxf(tm1, fmaxf(sacc[nb][2], sacc[nb][3]));
        }
        tm0 = qmax(tm0);
        tm1 = qmax(tm1);
        float mn0 = fmaxf(m0, tm0);
        float mn1 = fmaxf(m1, tm1);
        float a0 = __expf(m0 - mn0);
        float a1 = __expf(m1 - mn1);
        m0 = mn0; m1 = mn1;

        float ps0 = 0.f, ps1 = 0.f;
        #pragma unroll
        for (int nb = 0; nb < 8; nb++) {
            float p00 = __expf(sacc[nb][0] - mn0);
            float p01 = __expf(sacc[nb][1] - mn0);
            float p10 = __expf(sacc[nb][2] - mn1);
            float p11 = __expf(sacc[nb][3] - mn1);
            ps0 += p00 + p01;
            ps1 += p10 + p11;
            sacc[nb][0] = p00; sacc[nb][1] = p01;
            sacc[nb][2] = p10; sacc[nb][3] = p11;
        }
        ps0 = qsum(ps0);
        ps1 = qsum(ps1);
        l0 = l0 * a0 + ps0;
        l1 = l1 * a1 + ps1;

        #pragma unroll
        for (int nb = 0; nb < 8; nb++) {
            oacc[nb][0] *= a0; oacc[nb][1] *= a0;
            oacc[nb][2] *= a1; oacc[nb][3] *= a1;
        }

        // ---- store P (tf32-rounded) to this warp's own sP rows ----
        #pragma unroll
        for (int nb = 0; nb < 8; nb++) {
            *(float2*)&sP[r0 * LD + nb * 8 + 2 * tq] =
                make_float2(tf32r(sacc[nb][0]), tf32r(sacc[nb][1]));
            *(float2*)&sP[r1 * LD + nb * 8 + 2 * tq] =
                make_float2(tf32r(sacc[nb][2]), tf32r(sacc[nb][3]));
        }
        __syncwarp();   // P rows are per-warp private: warp-level sync suffices

        // ---- O += P V : per-warp 16 x 64, 64 mmas ----
        #pragma unroll
        for (int kb = 0; kb < 8; kb++) {
            uint32_t af[4];
            af[0] = uP[r0 * LD + kb * 8 + tq];
            af[1] = uP[r1 * LD + kb * 8 + tq];
            af[2] = uP[r0 * LD + kb * 8 + tq + 4];
            af[3] = uP[r1 * LD + kb * 8 + tq + 4];
            #pragma unroll
            for (int nb = 0; nb < 8; nb++) {
                uint32_t b0 = uV[(kb * 8 + tq) * LD + nb * 8 + g];
                uint32_t b1 = uV[(kb * 8 + tq + 4) * LD + nb * 8 + g];
                mma8(oacc[nb], af, b0, b1);
            }
        }
    }

    // ---- epilogue ----
    float inv0 = 1.0f / l0;
    float inv1 = 1.0f / l1;
    #pragma unroll
    for (int nb = 0; nb < 8; nb++) {
        *(float2*)&Og[(size_t)r0 * DH + nb * 8 + 2 * tq] =
            make_float2(oacc[nb][0] * inv0, oacc[nb][1] * inv0);
        *(float2*)&Og[(size_t)r1 * DH + nb * 8 + 2 * tq] =
            make_float2(oacc[nb][2] * inv1, oacc[nb][3] * inv1);
    }
}

extern "C" void kernel_launch(void* const* d_in, const int* in_sizes, int n_in,
                              void* d_out, int out_size) {
    const float* q = (const float*)d_in[0];
    const float* k = (const float*)d_in[1];
    const float* v = (const float*)d_in[2];
    // d_in[3] = mask: known causal tril, applied analytically.
    float* o = (float*)d_out;

    cudaFuncSetAttribute(fa_mma_kernel,
                         cudaFuncAttributeMaxDynamicSharedMemorySize, SMEM_BYTES);

    dim3 grid(S_LEN / BQ, 64 /* B*H */);
    fa_mma_kernel<<<grid, NT, SMEM_BYTES>>>(q, k, v, o);
}

// round 6
// speedup vs baseline: 1.0050x; 1.0050x over previous
#include <cuda_runtime.h>
#include <cstdint>

// Causal SDPA, B=4 H=16 S=2048 D=64, fp32 I/O.
// FA2-style flash attention on mma.sync.m16n8k8 tf32 (base sm_100 target — no tcgen05).
// 8 warps x 16 q-rows, BK=64 kv tiles, Q fragments register-resident,
// K/V/P pre-rounded to tf32 in smem, online softmax in registers.

#define BQ 128
#define BK 64
#define DH 64
#define NT 256
#define LD 68            // smem row stride in floats (272 B): conflict-free frag loads
#define SCALE 0.125f
#define NEG_BIG (-1.0e30f)

static constexpr int S_LEN = 2048;
static constexpr int SK_OFF = 0;              // K tile  [64][LD]
static constexpr int SV_OFF = BK * LD;        // V tile  [64][LD]
static constexpr int SP_OFF = 2 * BK * LD;    // P tile / Q staging [128][LD]
static constexpr int SMEM_BYTES = (2 * BK * LD + BQ * LD) * 4;  // 69632 B

__device__ __forceinline__ float tf32r(float x) {
    uint32_t y;
    asm("cvt.rna.tf32.f32 %0, %1;" : "=r"(y) : "f"(x));
    return __uint_as_float(y);
}

__device__ __forceinline__ void mma8(float c[4], const uint32_t a[4],
                                     uint32_t b0, uint32_t b1) {
    asm volatile(
        "mma.sync.aligned.m16n8k8.row.col.f32.tf32.tf32.f32 "
        "{%0,%1,%2,%3}, {%4,%5,%6,%7}, {%8,%9}, {%0,%1,%2,%3};"
        : "+f"(c[0]), "+f"(c[1]), "+f"(c[2]), "+f"(c[3])
        : "r"(a[0]), "r"(a[1]), "r"(a[2]), "r"(a[3]), "r"(b0), "r"(b1));
}

__device__ __forceinline__ float qmax(float v) {
    v = fmaxf(v, __shfl_xor_sync(0xffffffffu, v, 1));
    v = fmaxf(v, __shfl_xor_sync(0xffffffffu, v, 2));
    return v;
}
__device__ __forceinline__ float qsum(float v) {
    v += __shfl_xor_sync(0xffffffffu, v, 1);
    v += __shfl_xor_sync(0xffffffffu, v, 2);
    return v;
}

__global__ __launch_bounds__(NT, 2)
void fa_mma_kernel(const float* __restrict__ Q,
                   const float* __restrict__ K,
                   const float* __restrict__ V,
                   float* __restrict__ O) {
    extern __shared__ float sm[];
    float* sK = sm + SK_OFF;
    float* sV = sm + SV_OFF;
    float* sP = sm + SP_OFF;
    const uint32_t* uK = (const uint32_t*)sK;
    const uint32_t* uV = (const uint32_t*)sV;
    const uint32_t* uP = (const uint32_t*)sP;

    const int tid  = threadIdx.x;
    const int warp = tid >> 5;
    const int lane = tid & 31;
    const int g    = lane >> 2;   // group id (row within 8)
    const int tq   = lane & 3;    // thread-in-group (col quad)

    const int r0 = warp * 16 + g;     // local q row (a0/a2, c0/c1)
    const int r1 = r0 + 8;            // local q row (a1/a3, c2/c3)

    const int bh = blockIdx.y;
    const int qt = (int)(gridDim.x - 1) - (int)blockIdx.x;  // heavy tiles first
    const int q0 = qt * BQ;

    const float* Qg = Q + ((size_t)bh * S_LEN + q0) * DH;
    const float* Kg = K + (size_t)bh * S_LEN * DH;
    const float* Vg = V + (size_t)bh * S_LEN * DH;
    float*       Og = O + ((size_t)bh * S_LEN + q0) * DH;

    // ---- stage Q (scaled + tf32-rounded) into sP, then lift fragments to regs ----
    for (int i = tid; i < BQ * (DH / 4); i += NT) {
        int row = i >> 4;
        int c4  = (i & 15) << 2;
        float4 v = *(const float4*)(Qg + (size_t)row * DH + c4);
        v.x = tf32r(v.x * SCALE); v.y = tf32r(v.y * SCALE);
        v.z = tf32r(v.z * SCALE); v.w = tf32r(v.w * SCALE);
        *(float4*)&sP[row * LD + c4] = v;
    }
    __syncthreads();

    uint32_t qf[8][4];
    #pragma unroll
    for (int kb = 0; kb < 8; kb++) {
        qf[kb][0] = uP[r0 * LD + kb * 8 + tq];
        qf[kb][1] = uP[r1 * LD + kb * 8 + tq];
        qf[kb][2] = uP[r0 * LD + kb * 8 + tq + 4];
        qf[kb][3] = uP[r1 * LD + kb * 8 + tq + 4];
    }

    float oacc[8][4];
    #pragma unroll
    for (int nb = 0; nb < 8; nb++)
        #pragma unroll
        for (int j = 0; j < 4; j++) oacc[nb][j] = 0.f;
    float m0 = NEG_BIG, m1 = NEG_BIG, l0 = 0.f, l1 = 0.f;

    const int ntiles = 2 * qt + 2;   // kv tiles needed for causal coverage
    for (int kt = 0; kt < ntiles; kt++) {
        const int kv0 = kt * BK;

        __syncthreads();  // previous iteration's readers done with sK/sV

        // ---- stage K,V tiles (tf32-rounded) ----
        for (int i = tid; i < BK * (DH / 4); i += NT) {
            int row = i >> 4;
            int c4  = (i & 15) << 2;
            float4 kv = *(const float4*)(Kg + (size_t)(kv0 + row) * DH + c4);
            kv.x = tf32r(kv.x); kv.y = tf32r(kv.y);
            kv.z = tf32r(kv.z); kv.w = tf32r(kv.w);
            *(float4*)&sK[row * LD + c4] = kv;
            float4 vv = *(const float4*)(Vg + (size_t)(kv0 + row) * DH + c4);
            vv.x = tf32r(vv.x); vv.y = tf32r(vv.y);
            vv.z = tf32r(vv.z); vv.w = tf32r(vv.w);
            *(float4*)&sV[row * LD + c4] = vv;
        }
        __syncthreads();

        // ---- S = Q K^T : per-warp 16 x 64, 64 mmas ----
        float sacc[8][4];
        #pragma unroll
        for (int nb = 0; nb < 8; nb++)
            #pragma unroll
            for (int j = 0; j < 4; j++) sacc[nb][j] = 0.f;

        #pragma unroll
        for (int kb = 0; kb < 8; kb++) {
            #pragma unroll
            for (int nb = 0; nb < 8; nb++) {
                uint32_t b0 = uK[(nb * 8 + g) * LD + kb * 8 + tq];
                uint32_t b1 = uK[(nb * 8 + g) * LD + kb * 8 + tq + 4];
                mma8(sacc[nb], qf[kb], b0, b1);
            }
        }

        // ---- causal mask (only last two kv tiles intersect the diagonal) ----
        if (kt >= ntiles - 2) {
            const int qr0 = q0 + r0;
            const int qr1 = q0 + r1;
            #pragma unroll
            for (int nb = 0; nb < 8; nb++) {
                int c = kv0 + nb * 8 + 2 * tq;
                if (c     > qr0) sacc[nb][0] = NEG_BIG;
                if (c + 1 > qr0) sacc[nb][1] = NEG_BIG;
                if (c     > qr1) sacc[nb][2] = NEG_BIG;
                if (c + 1 > qr1) sacc[nb][3] = NEG_BIG;
            }
        }

        // ---- online softmax ----
        float tm0 = NEG_BIG, tm1 = NEG_BIG;
        #pragma unroll
        for (int nb = 0; nb < 8; nb++) {
            tm0 = fmaxf(tm0, fmaxf(sacc[nb][0], sacc[nb][1]));
            tm1 = fmaxf(tm1, fmaxf(sacc[nb][2], sacc[nb][3]));
        }
        tm0 = qmax(tm0);
        tm1 = qmax(tm1);
        float mn0 = fmaxf(m0, tm0);
        float mn1 = fmaxf(m1, tm1);
        float a0 = __expf(m0 - mn0);
        float a1 = __expf(m1 - mn1);
        m0 = mn0; m1 = mn1;

        float ps0 = 0.f, ps1 = 0.f;
        #pragma unroll
        for (int nb = 0; nb < 8; nb++) {
            float p00 = __expf(sacc[nb][0] - mn0);
            float p01 = __expf(sacc[nb][1] - mn0);
            float p10 = __expf(sacc[nb][2] - mn1);
            float p11 = __expf(sacc[nb][3] - mn1);
            ps0 += p00 + p01;
            ps1 += p10 + p11;
            sacc[nb][0] = p00; sacc[nb][1] = p01;
            sacc[nb][2] = p10; sacc[nb][3] = p11;
        }
        ps0 = qsum(ps0);
        ps1 = qsum(ps1);
        l0 = l0 * a0 + ps0;
        l1 = l1 * a1 + ps1;

        #pragma unroll
        for (int nb = 0; nb < 8; nb++) {
            oacc[nb][0] *= a0; oacc[nb][1] *= a0;
            oacc[nb][2] *= a1; oacc[nb][3] *= a1;
        }

        // ---- store P (tf32-rounded) to this warp's own sP rows ----
        #pragma unroll
        for (int nb = 0; nb < 8; nb++) {
            *(float2*)&sP[r0 * LD + nb * 8 + 2 * tq] =
                make_float2(tf32r(sacc[nb][0]), tf32r(sacc[nb][1]));
            *(float2*)&sP[r1 * LD + nb * 8 + 2 * tq] =
                make_float2(tf32r(sacc[nb][2]), tf32r(sacc[nb][3]));
        }
        __syncwarp();   // P rows are per-warp private: warp-level sync suffices

        // ---- O += P V : per-warp 16 x 64, 64 mmas ----
        #pragma unroll
        for (int kb = 0; kb < 8; kb++) {
            uint32_t af[4];
            af[0] = uP[r0 * LD + kb * 8 + tq];
            af[1] = uP[r1 * LD + kb * 8 + tq];
            af[2] = uP[r0 * LD + kb * 8 + tq + 4];
            af[3] = uP[r1 * LD + kb * 8 + tq + 4];
            #pragma unroll
            for (int nb = 0; nb < 8; nb++) {
                uint32_t b0 = uV[(kb * 8 + tq) * LD + nb * 8 + g];
                uint32_t b1 = uV[(kb * 8 + tq + 4) * LD + nb * 8 + g];
                mma8(oacc[nb], af, b0, b1);
            }
        }
    }

    // ---- epilogue ----
    float inv0 = 1.0f / l0;
    float inv1 = 1.0f / l1;
    #pragma unroll
    for (int nb = 0; nb < 8; nb++) {
        *(float2*)&Og[(size_t)r0 * DH + nb * 8 + 2 * tq] =
            make_float2(oacc[nb][0] * inv0, oacc[nb][1] * inv0);
        *(float2*)&Og[(size_t)r1 * DH + nb * 8 + 2 * tq] =
            make_float2(oacc[nb][2] * inv1, oacc[nb][3] * inv1);
    }
}

extern "C" void kernel_launch(void* const* d_in, const int* in_sizes, int n_in,
                              void* d_out, int out_size) {
    const float* q = (const float*)d_in[0];
    const float* k = (const float*)d_in[1];
    const float* v = (const float*)d_in[2];
    // d_in[3] = mask: known causal tril, applied analytically.
    float* o = (float*)d_out;

    cudaFuncSetAttribute(fa_mma_kernel,
                         cudaFuncAttributeMaxDynamicSharedMemorySize, SMEM_BYTES);

    dim3 grid(S_LEN / BQ, 64 /* B*H */);
    fa_mma_kernel<<<grid, NT, SMEM_BYTES>>>(q, k, v, o);
}